// round 7
// baseline (speedup 1.0000x reference)
#include <cuda_runtime.h>
#include <cuda_fp16.h>

#define HD 64
#define FULL 0xFFFFFFFFu

static const int N_CAP = 100000;
static const int E_CAP = 1200000;
static const int G_CAP = 256;

// Scratch (allocation-free: __device__ globals; only referenced in device code)
__device__ int    g_deg[N_CAP];
__device__ int    g_off[N_CAP];
__device__ int    g_cur[N_CAP];
__device__ int    g_total;
__device__ int2   g_csr[E_CAP];          // {src, w bits}
__device__ __half g_h1[N_CAP * HD];      // fp16 node features (layer1 out)
__device__ __half g_h2[N_CAP * HD];      // fp16 node features (layer2 out)
__device__ float  g_sums[G_CAP * HD];
__device__ float  g_cnt[G_CAP];

__device__ __forceinline__ void red_add_v4(float* p, float4 v) {
    asm volatile("red.global.add.v4.f32 [%0], {%1,%2,%3,%4};"
                 :: "l"(p), "f"(v.x), "f"(v.y), "f"(v.z), "f"(v.w) : "memory");
}

// ---------------- init: zero deg / sums / cnt / total ----------------
__global__ void init_kernel(int n, int g) {
    int i = blockIdx.x * blockDim.x + threadIdx.x;
    int stride = gridDim.x * blockDim.x;
    for (int k = i; k < n; k += stride) g_deg[k] = 0;
    int sv = g * HD;
    for (int k = i; k < sv; k += stride) g_sums[k] = 0.f;
    for (int k = i; k < g; k += stride) g_cnt[k] = 0.f;
    if (i == 0) g_total = 0;
}

// ---------------- CSR build ----------------
__global__ void hist_kernel(const int* __restrict__ dst, int E) {
    int t = blockIdx.x * blockDim.x + threadIdx.x;
    int i = t * 4;
    if (i + 3 < E) {
        int4 d = __ldg((const int4*)(dst + i));
        atomicAdd(&g_deg[d.x], 1);
        atomicAdd(&g_deg[d.y], 1);
        atomicAdd(&g_deg[d.z], 1);
        atomicAdd(&g_deg[d.w], 1);
    } else {
        for (int e = i; e < E; e++) atomicAdd(&g_deg[dst[e]], 1);
    }
}

// segment order in memory is irrelevant -> no scan needed, one atomic cursor
__global__ void offs_kernel(int n) {
    int i = blockIdx.x * blockDim.x + threadIdx.x;
    if (i >= n) return;
    int d = g_deg[i];
    int o = atomicAdd(&g_total, d);
    g_off[i] = o;
    g_cur[i] = o;
}

__global__ void fill_kernel(const int* __restrict__ src, const int* __restrict__ dst,
                            const float* __restrict__ ew, int E) {
    int e0 = (blockIdx.x * blockDim.x + threadIdx.x) * 2;
    if (e0 >= E) return;
    int d0 = __ldg(dst + e0), s0 = __ldg(src + e0);
    float w0 = __ldg(ew + e0);
    int e1 = e0 + 1;
    int d1 = 0, s1 = 0; float w1 = 0.f;
    bool has1 = e1 < E;
    if (has1) { d1 = __ldg(dst + e1); s1 = __ldg(src + e1); w1 = __ldg(ew + e1); }
    int p0 = atomicAdd(&g_cur[d0], 1);
    g_csr[p0] = make_int2(s0, __float_as_int(w0));
    if (has1) {
        int p1 = atomicAdd(&g_cur[d1], 1);
        g_csr[p1] = make_int2(s1, __float_as_int(w1));
    }
}

// ---------------- layer 1 fused: agg (C=1 gather) + node transform + graph counts ----
// warp per node; h1 stored fp16
__global__ void layer1_kernel(const float* __restrict__ x, const int* __restrict__ batch,
                              const float* __restrict__ Wrel, const float* __restrict__ b,
                              const float* __restrict__ Wroot, int n) {
    int gtid = blockIdx.x * blockDim.x + threadIdx.x;
    int node = gtid >> 5, lane = gtid & 31;
    if (node >= n) return;

    int off = g_off[node], deg = g_deg[node], end = off + deg;
    float a = 0.f;
    for (int i = off + lane; i < end; i += 32) {
        int2 p = __ldg(g_csr + i);
        a = fmaf(__int_as_float(p.y), __ldg(x + p.x), a);
    }
#pragma unroll
    for (int s = 16; s > 0; s >>= 1) a += __shfl_xor_sync(FULL, a, s);

    float xv = __ldg(x + node);
    float wr0 = __ldg(Wrel + lane), wr1 = __ldg(Wrel + 32 + lane);
    float wo0 = __ldg(Wroot + lane), wo1 = __ldg(Wroot + 32 + lane);
    float b0 = __ldg(b + lane), b1 = __ldg(b + 32 + lane);
    float h0 = fmaxf(fmaf(a, wr0, fmaf(xv, wo0, b0)), 0.f);
    float h1 = fmaxf(fmaf(a, wr1, fmaf(xv, wo1, b1)), 0.f);
    g_h1[node * HD + lane]      = __float2half_rn(h0);
    g_h1[node * HD + 32 + lane] = __float2half_rn(h1);
    if (lane == 0) atomicAdd(&g_cnt[batch[node]], 1.0f);
}

// ---------------- gemm inner: acc += sA[nodes][k] * sW[k][channels] -----------------
__device__ __forceinline__ void gemm_pass(const float* sW, const float* sA,
                                          int cg, int ng, float4* accA, float4* accB) {
#pragma unroll 2
    for (int k4 = 0; k4 < 16; k4++) {
        float4 xv[4];
#pragma unroll
        for (int r = 0; r < 4; r++)
            xv[r] = *(const float4*)(sA + (ng * 4 + r) * 64 + k4 * 4);
#pragma unroll
        for (int kk = 0; kk < 4; kk++) {
            int k = k4 * 4 + kk;
            float4 w0 = *(const float4*)(sW + k * 64 + cg * 8);
            float4 w1 = *(const float4*)(sW + k * 64 + cg * 8 + 4);
#pragma unroll
            for (int r = 0; r < 4; r++) {
                float xs = (kk == 0) ? xv[r].x : (kk == 1) ? xv[r].y
                         : (kk == 2) ? xv[r].z : xv[r].w;
                accA[r].x = fmaf(xs, w0.x, accA[r].x);
                accA[r].y = fmaf(xs, w0.y, accA[r].y);
                accA[r].z = fmaf(xs, w0.z, accA[r].z);
                accA[r].w = fmaf(xs, w0.w, accA[r].w);
                accB[r].x = fmaf(xs, w1.x, accB[r].x);
                accB[r].y = fmaf(xs, w1.y, accB[r].y);
                accB[r].z = fmaf(xs, w1.z, accB[r].z);
                accB[r].w = fmaf(xs, w1.w, accB[r].w);
            }
        }
    }
}

// ---------------- fused H-layer: aggregate (CSR gather) + node GEMM ------------------
// 128-node tile, 256 threads. Phase 1: 8 warps x 16 nodes -> sA[node][k] in smem.
// Phase 2: two K=64 gemm passes (agg@Wrel then hin@Wroot) sharing fp32 accumulators.
// LAYER==2: relu + fp16 store to g_h2.  LAYER==3: pool via red into g_sums.
template <int LAYER>
__global__ void __launch_bounds__(256, 4) fused_kernel(
        const float* __restrict__ Wrel, const float* __restrict__ Wroot,
        const float* __restrict__ bias, const int* __restrict__ batch, int n) {
    __shared__ float smem[64 * 64 + 128 * 64];
    float* sW = smem;            // [k][j]   16KB
    float* sA = smem + 64 * 64;  // [node][k] 32KB
    const __half* Hin = (LAYER == 2) ? g_h1 : g_h2;
    int tid = threadIdx.x;
    int lane = tid & 31, w = tid >> 5;
    int n0 = blockIdx.x * 128;

    // preload Wrel (overlaps phase-1 gather latency)
    for (int i = tid; i < 1024; i += 256)
        ((float4*)sW)[i] = __ldg((const float4*)Wrel + i);

    // ---- phase 1: aggregation, warp w handles nodes n0 + w*16 .. +15 ----
#pragma unroll 1
    for (int t = 0; t < 16; t++) {
        int ln = w * 16 + t;
        int node = n0 + ln;
        float a0 = 0.f, a1 = 0.f;
        if (node < n) {
            int off = g_off[node], end = off + g_deg[node];
            int i = off;
#pragma unroll 1
            for (; i + 4 <= end; i += 4) {
                int2 p0 = __ldg(g_csr + i);
                int2 p1 = __ldg(g_csr + i + 1);
                int2 p2 = __ldg(g_csr + i + 2);
                int2 p3 = __ldg(g_csr + i + 3);
                __half2 v0 = __ldg((const __half2*)(Hin + p0.x * HD) + lane);
                __half2 v1 = __ldg((const __half2*)(Hin + p1.x * HD) + lane);
                __half2 v2 = __ldg((const __half2*)(Hin + p2.x * HD) + lane);
                __half2 v3 = __ldg((const __half2*)(Hin + p3.x * HD) + lane);
                float2 f0 = __half22float2(v0);
                float2 f1 = __half22float2(v1);
                float2 f2 = __half22float2(v2);
                float2 f3 = __half22float2(v3);
                float w0 = __int_as_float(p0.y), w1 = __int_as_float(p1.y);
                float w2 = __int_as_float(p2.y), w3 = __int_as_float(p3.y);
                a0 = fmaf(w0, f0.x, a0); a1 = fmaf(w0, f0.y, a1);
                a0 = fmaf(w1, f1.x, a0); a1 = fmaf(w1, f1.y, a1);
                a0 = fmaf(w2, f2.x, a0); a1 = fmaf(w2, f2.y, a1);
                a0 = fmaf(w3, f3.x, a0); a1 = fmaf(w3, f3.y, a1);
            }
            for (; i < end; i++) {
                int2 p = __ldg(g_csr + i);
                __half2 v = __ldg((const __half2*)(Hin + p.x * HD) + lane);
                float2 f = __half22float2(v);
                float ww = __int_as_float(p.y);
                a0 = fmaf(ww, f.x, a0); a1 = fmaf(ww, f.y, a1);
            }
        }
        ((float2*)(sA + ln * 64))[lane] = make_float2(a0, a1);
    }
    __syncthreads();

    // ---- phase 2 ----
    int cg = tid & 7;        // channels cg*8 .. +7
    int ng = tid >> 3;       // nodes ng*4 .. +3
    float4 accA[4], accB[4];
#pragma unroll
    for (int r = 0; r < 4; r++) {
        accA[r] = make_float4(0.f, 0.f, 0.f, 0.f);
        accB[r] = make_float4(0.f, 0.f, 0.f, 0.f);
    }

    gemm_pass(sW, sA, cg, ng, accA, accB);   // pass 0: agg @ Wrel
    __syncthreads();

    // restage: sW <- Wroot, sA <- Hin (fp16 -> fp32)
    for (int i = tid; i < 1024; i += 256)
        ((float4*)sW)[i] = __ldg((const float4*)Wroot + i);
    for (int i = tid; i < 2048; i += 256) {
        int node = i >> 4, c4 = i & 15;
        int gn = n0 + node;
        float4 v = make_float4(0.f, 0.f, 0.f, 0.f);
        if (gn < n) {
            int2 raw = __ldg((const int2*)(Hin + gn * HD) + c4);
            float2 f0 = __half22float2(*(__half2*)&raw.x);
            float2 f1 = __half22float2(*(__half2*)&raw.y);
            v = make_float4(f0.x, f0.y, f1.x, f1.y);
        }
        *(float4*)(sA + node * 64 + c4 * 4) = v;
    }
    __syncthreads();

    gemm_pass(sW, sA, cg, ng, accA, accB);   // pass 1: hin @ Wroot

    // ---- epilogue ----
    float4 bb0 = __ldg((const float4*)bias + cg * 2);
    float4 bb1 = __ldg((const float4*)bias + cg * 2 + 1);
#pragma unroll
    for (int r = 0; r < 4; r++) {
        int gn = n0 + ng * 4 + r;
        if (gn >= n) break;
        float4 oa = accA[r], ob = accB[r];
        oa.x += bb0.x; oa.y += bb0.y; oa.z += bb0.z; oa.w += bb0.w;
        ob.x += bb1.x; ob.y += bb1.y; ob.z += bb1.z; ob.w += bb1.w;
        if (LAYER == 2) {
            oa.x = fmaxf(oa.x, 0.f); oa.y = fmaxf(oa.y, 0.f);
            oa.z = fmaxf(oa.z, 0.f); oa.w = fmaxf(oa.w, 0.f);
            ob.x = fmaxf(ob.x, 0.f); ob.y = fmaxf(ob.y, 0.f);
            ob.z = fmaxf(ob.z, 0.f); ob.w = fmaxf(ob.w, 0.f);
            __half2 h01 = __floats2half2_rn(oa.x, oa.y);
            __half2 h23 = __floats2half2_rn(oa.z, oa.w);
            __half2 h45 = __floats2half2_rn(ob.x, ob.y);
            __half2 h67 = __floats2half2_rn(ob.z, ob.w);
            int4 packed = make_int4(*(int*)&h01, *(int*)&h23, *(int*)&h45, *(int*)&h67);
            *(int4*)(g_h2 + gn * HD + cg * 8) = packed;
        } else {
            float* sp = g_sums + batch[gn] * HD + cg * 8;
            red_add_v4(sp, oa);
            red_add_v4(sp + 4, ob);
        }
    }
}

// ---------------- head ----------------
__global__ void head_kernel(const float* __restrict__ Wlin, const float* __restrict__ blin,
                            float* __restrict__ out, int g) {
    int idx = blockIdx.x * blockDim.x + threadIdx.x;
    if (idx >= g * 2) return;
    int gi = idx >> 1, c = idx & 1;
    float inv = 1.0f / fmaxf(g_cnt[gi], 1.0f);
    float acc = 0.f;
#pragma unroll
    for (int k = 0; k < HD; k++)
        acc = fmaf(g_sums[gi * HD + k], Wlin[k * 2 + c], acc);
    out[idx] = fmaf(acc, inv, blin[c]);
}

extern "C" void kernel_launch(void* const* d_in, const int* in_sizes, int n_in,
                              void* d_out, int out_size) {
    const float* x      = (const float*)d_in[0];
    const int*   ei     = (const int*)d_in[1];
    const int*   batch  = (const int*)d_in[2];
    const float* ew     = (const float*)d_in[3];
    const float* W1rel  = (const float*)d_in[4];
    const float* b1     = (const float*)d_in[5];
    const float* W1root = (const float*)d_in[6];
    const float* W2rel  = (const float*)d_in[7];
    const float* b2     = (const float*)d_in[8];
    const float* W2root = (const float*)d_in[9];
    const float* W3rel  = (const float*)d_in[10];
    const float* b3     = (const float*)d_in[11];
    const float* W3root = (const float*)d_in[12];
    const float* Wlin   = (const float*)d_in[13];
    const float* blin   = (const float*)d_in[14];

    int N = in_sizes[0];        // x is [N,1]
    int E = in_sizes[3];        // edge_weight is [E]
    int G = out_size / 2;

    const int* src = ei;
    const int* dst = ei + E;
    float* out = (float*)d_out;

    init_kernel<<<256, 256>>>(N, G);
    hist_kernel<<<(E / 4 + 256) / 256, 256>>>(dst, E);
    offs_kernel<<<(N + 255) / 256, 256>>>(N);
    fill_kernel<<<(E / 2 + 256) / 256, 256>>>(src, dst, ew, E);

    layer1_kernel<<<(N * 32 + 255) / 256, 256>>>(x, batch, W1rel, b1, W1root, N);
    fused_kernel<2><<<(N + 127) / 128, 256>>>(W2rel, W2root, b2, batch, N);
    fused_kernel<3><<<(N + 127) / 128, 256>>>(W3rel, W3root, b3, batch, N);
    head_kernel<<<(G * 2 + 255) / 256, 256>>>(Wlin, blin, out, G);
}

// round 8
// speedup vs baseline: 1.2437x; 1.2437x over previous
#include <cuda_runtime.h>
#include <cuda_fp16.h>

#define HD 64
#define FULL 0xFFFFFFFFu

static const int N_CAP = 100000;
static const int E_CAP = 1200000;
static const int G_CAP = 256;

// Scratch (allocation-free: __device__ globals; only referenced in device code)
__device__ int    g_deg[N_CAP];
__device__ int    g_off[N_CAP];
__device__ int    g_cur[N_CAP];
__device__ int    g_total;
__device__ int2   g_csr[E_CAP];          // {src, w bits}
__device__ __half g_h1[N_CAP * HD];      // fp16 node features (layer1 out)
__device__ __half g_h2[N_CAP * HD];      // fp16 node features (layer2 out)
__device__ float  g_agg[N_CAP * HD];     // fp32 aggregation result
__device__ float  g_sums[G_CAP * HD];
__device__ float  g_cnt[G_CAP];

__device__ __forceinline__ void red_add_v4(float* p, float4 v) {
    asm volatile("red.global.add.v4.f32 [%0], {%1,%2,%3,%4};"
                 :: "l"(p), "f"(v.x), "f"(v.y), "f"(v.z), "f"(v.w) : "memory");
}

// ---------------- init: zero deg / sums / cnt / total ----------------
__global__ void init_kernel(int n, int g) {
    int i = blockIdx.x * blockDim.x + threadIdx.x;
    int stride = gridDim.x * blockDim.x;
    for (int k = i; k < n; k += stride) g_deg[k] = 0;
    int sv = g * HD;
    for (int k = i; k < sv; k += stride) g_sums[k] = 0.f;
    for (int k = i; k < g; k += stride) g_cnt[k] = 0.f;
    if (i == 0) g_total = 0;
}

// ---------------- CSR build ----------------
__global__ void hist_kernel(const int* __restrict__ dst, int E) {
    int t = blockIdx.x * blockDim.x + threadIdx.x;
    int i = t * 4;
    if (i + 3 < E) {
        int4 d = __ldg((const int4*)(dst + i));
        atomicAdd(&g_deg[d.x], 1);
        atomicAdd(&g_deg[d.y], 1);
        atomicAdd(&g_deg[d.z], 1);
        atomicAdd(&g_deg[d.w], 1);
    } else {
        for (int e = i; e < E; e++) atomicAdd(&g_deg[dst[e]], 1);
    }
}

// segment order in memory is irrelevant -> no scan needed, one atomic cursor
__global__ void offs_kernel(int n) {
    int i = blockIdx.x * blockDim.x + threadIdx.x;
    if (i >= n) return;
    int d = g_deg[i];
    int o = atomicAdd(&g_total, d);
    g_off[i] = o;
    g_cur[i] = o;
}

__global__ void fill_kernel(const int* __restrict__ src, const int* __restrict__ dst,
                            const float* __restrict__ ew, int E) {
    int e0 = (blockIdx.x * blockDim.x + threadIdx.x) * 2;
    if (e0 >= E) return;
    int d0 = __ldg(dst + e0), s0 = __ldg(src + e0);
    float w0 = __ldg(ew + e0);
    int e1 = e0 + 1;
    int d1 = 0, s1 = 0; float w1 = 0.f;
    bool has1 = e1 < E;
    if (has1) { d1 = __ldg(dst + e1); s1 = __ldg(src + e1); w1 = __ldg(ew + e1); }
    int p0 = atomicAdd(&g_cur[d0], 1);
    g_csr[p0] = make_int2(s0, __float_as_int(w0));
    if (has1) {
        int p1 = atomicAdd(&g_cur[d1], 1);
        g_csr[p1] = make_int2(s1, __float_as_int(w1));
    }
}

// ---------------- layer 1 fused: agg (C=1 gather) + node transform + graph counts ----
// warp per node; h1 stored fp16
__global__ void layer1_kernel(const float* __restrict__ x, const int* __restrict__ batch,
                              const float* __restrict__ Wrel, const float* __restrict__ b,
                              const float* __restrict__ Wroot, int n) {
    int gtid = blockIdx.x * blockDim.x + threadIdx.x;
    int node = gtid >> 5, lane = gtid & 31;
    if (node >= n) return;

    int off = g_off[node], deg = g_deg[node], end = off + deg;
    float a = 0.f;
    for (int i = off + lane; i < end; i += 32) {
        int2 p = __ldg(g_csr + i);
        a = fmaf(__int_as_float(p.y), __ldg(x + p.x), a);
    }
#pragma unroll
    for (int s = 16; s > 0; s >>= 1) a += __shfl_xor_sync(FULL, a, s);

    float xv = __ldg(x + node);
    float wr0 = __ldg(Wrel + lane), wr1 = __ldg(Wrel + 32 + lane);
    float wo0 = __ldg(Wroot + lane), wo1 = __ldg(Wroot + 32 + lane);
    float b0 = __ldg(b + lane), b1 = __ldg(b + 32 + lane);
    float h0 = fmaxf(fmaf(a, wr0, fmaf(xv, wo0, b0)), 0.f);
    float h1 = fmaxf(fmaf(a, wr1, fmaf(xv, wo1, b1)), 0.f);
    g_h1[node * HD + lane]      = __float2half_rn(h0);
    g_h1[node * HD + 32 + lane] = __float2half_rn(h1);
    if (lane == 0) atomicAdd(&g_cnt[batch[node]], 1.0f);
}

// ---------------- H-layer aggregation: warp-per-node, lane = channel pair ----------
// Per edge: one warp-uniform CSR load (broadcast) + one half2 gather per lane.
// Main loop: 8 edges per trip (8 independent row loads in flight) -> 4 -> 1.
template <int LAYER>
__global__ void aggH_kernel(int n) {
    const __half* __restrict__ hin = (LAYER == 2) ? g_h1 : g_h2;
    int gtid = blockIdx.x * blockDim.x + threadIdx.x;
    int node = gtid >> 5, lane = gtid & 31;
    if (node >= n) return;

    int off = g_off[node], end = off + g_deg[node];
    float a0 = 0.f, a1 = 0.f;

    int i = off;
#pragma unroll 1
    for (; i + 8 <= end; i += 8) {
        int2 p[8];
#pragma unroll
        for (int j = 0; j < 8; j++) p[j] = __ldg(g_csr + i + j);
        __half2 v[8];
#pragma unroll
        for (int j = 0; j < 8; j++)
            v[j] = __ldg((const __half2*)(hin + p[j].x * HD) + lane);
#pragma unroll
        for (int j = 0; j < 8; j++) {
            float2 f = __half22float2(v[j]);
            float w = __int_as_float(p[j].y);
            a0 = fmaf(w, f.x, a0); a1 = fmaf(w, f.y, a1);
        }
    }
#pragma unroll 1
    for (; i + 4 <= end; i += 4) {
        int2 p[4];
#pragma unroll
        for (int j = 0; j < 4; j++) p[j] = __ldg(g_csr + i + j);
        __half2 v[4];
#pragma unroll
        for (int j = 0; j < 4; j++)
            v[j] = __ldg((const __half2*)(hin + p[j].x * HD) + lane);
#pragma unroll
        for (int j = 0; j < 4; j++) {
            float2 f = __half22float2(v[j]);
            float w = __int_as_float(p[j].y);
            a0 = fmaf(w, f.x, a0); a1 = fmaf(w, f.y, a1);
        }
    }
    for (; i < end; i++) {
        int2 p = __ldg(g_csr + i);
        __half2 v = __ldg((const __half2*)(hin + p.x * HD) + lane);
        float2 f = __half22float2(v);
        float w = __int_as_float(p.y);
        a0 = fmaf(w, f.x, a0); a1 = fmaf(w, f.y, a1);
    }
    ((float2*)(g_agg + node * HD))[lane] = make_float2(a0, a1);
}

// ---------------- fused node GEMM: out = agg @ Wrel + b + hin @ Wroot ----------------
// 128-node tile, 128 threads, 8x8 register tile, two K=64 passes sharing accumulators.
// pass0: X = g_agg (fp32). pass1: X = hin (fp16 -> fp32 on smem stage).
// LAYER==2: relu + store fp16 to g_h2.   LAYER==3: no relu, pool (red into g_sums).
template <int LAYER>
__global__ void __launch_bounds__(128, 4) gemm_kernel(
        const float* __restrict__ Wrel, const float* __restrict__ Wroot,
        const float* __restrict__ bias, const int* __restrict__ batch, int n) {
    __shared__ float sW[64 * 64];    // [k][j]
    __shared__ float sXT[64 * 128];  // [k][node]
    const __half* Hin = (LAYER == 2) ? g_h1 : g_h2;
    int tid = threadIdx.x;
    int cg = tid & 7;        // channels cg*8 .. cg*8+7
    int ng = tid >> 3;       // nodes ng*8 .. ng*8+7
    int n0 = blockIdx.x * 128;

    float4 accA[8], accB[8];
#pragma unroll
    for (int r = 0; r < 8; r++) {
        accA[r] = make_float4(0.f, 0.f, 0.f, 0.f);
        accB[r] = make_float4(0.f, 0.f, 0.f, 0.f);
    }

#pragma unroll
    for (int pass = 0; pass < 2; pass++) {
        const float* W = pass ? Wroot : Wrel;
        for (int i = tid; i < 1024; i += 128)
            ((float4*)sW)[i] = __ldg((const float4*)W + i);
        for (int i = tid; i < 2048; i += 128) {
            int node = i & 127, c4 = i >> 7;
            int gn = n0 + node;
            float4 v = make_float4(0.f, 0.f, 0.f, 0.f);
            if (gn < n) {
                if (pass == 0) {
                    v = __ldg((const float4*)(g_agg + gn * HD) + c4);
                } else {
                    int2 raw = __ldg((const int2*)(Hin + gn * HD) + c4);
                    float2 f0 = __half22float2(*(__half2*)&raw.x);
                    float2 f1 = __half22float2(*(__half2*)&raw.y);
                    v = make_float4(f0.x, f0.y, f1.x, f1.y);
                }
            }
            int k = c4 * 4;
            sXT[(k + 0) * 128 + node] = v.x;
            sXT[(k + 1) * 128 + node] = v.y;
            sXT[(k + 2) * 128 + node] = v.z;
            sXT[(k + 3) * 128 + node] = v.w;
        }
        __syncthreads();

#pragma unroll 8
        for (int k = 0; k < 64; k++) {
            float4 w0 = *(const float4*)(sW + k * 64 + cg * 8);
            float4 w1 = *(const float4*)(sW + k * 64 + cg * 8 + 4);
            float4 x0 = *(const float4*)(sXT + k * 128 + ng * 8);
            float4 x1 = *(const float4*)(sXT + k * 128 + ng * 8 + 4);
            float xs[8] = {x0.x, x0.y, x0.z, x0.w, x1.x, x1.y, x1.z, x1.w};
#pragma unroll
            for (int r = 0; r < 8; r++) {
                accA[r].x = fmaf(xs[r], w0.x, accA[r].x);
                accA[r].y = fmaf(xs[r], w0.y, accA[r].y);
                accA[r].z = fmaf(xs[r], w0.z, accA[r].z);
                accA[r].w = fmaf(xs[r], w0.w, accA[r].w);
                accB[r].x = fmaf(xs[r], w1.x, accB[r].x);
                accB[r].y = fmaf(xs[r], w1.y, accB[r].y);
                accB[r].z = fmaf(xs[r], w1.z, accB[r].z);
                accB[r].w = fmaf(xs[r], w1.w, accB[r].w);
            }
        }
        __syncthreads();
    }

    float4 bb0 = __ldg((const float4*)bias + cg * 2);
    float4 bb1 = __ldg((const float4*)bias + cg * 2 + 1);
#pragma unroll
    for (int r = 0; r < 8; r++) {
        int gn = n0 + ng * 8 + r;
        if (gn >= n) break;
        float4 oa = accA[r], ob = accB[r];
        oa.x += bb0.x; oa.y += bb0.y; oa.z += bb0.z; oa.w += bb0.w;
        ob.x += bb1.x; ob.y += bb1.y; ob.z += bb1.z; ob.w += bb1.w;
        if (LAYER == 2) {
            oa.x = fmaxf(oa.x, 0.f); oa.y = fmaxf(oa.y, 0.f);
            oa.z = fmaxf(oa.z, 0.f); oa.w = fmaxf(oa.w, 0.f);
            ob.x = fmaxf(ob.x, 0.f); ob.y = fmaxf(ob.y, 0.f);
            ob.z = fmaxf(ob.z, 0.f); ob.w = fmaxf(ob.w, 0.f);
            __half2 h01 = __floats2half2_rn(oa.x, oa.y);
            __half2 h23 = __floats2half2_rn(oa.z, oa.w);
            __half2 h45 = __floats2half2_rn(ob.x, ob.y);
            __half2 h67 = __floats2half2_rn(ob.z, ob.w);
            int4 packed = make_int4(*(int*)&h01, *(int*)&h23, *(int*)&h45, *(int*)&h67);
            *(int4*)(g_h2 + gn * HD + cg * 8) = packed;
        } else {
            float* sp = g_sums + batch[gn] * HD + cg * 8;
            red_add_v4(sp, oa);
            red_add_v4(sp + 4, ob);
        }
    }
}

// ---------------- head ----------------
__global__ void head_kernel(const float* __restrict__ Wlin, const float* __restrict__ blin,
                            float* __restrict__ out, int g) {
    int idx = blockIdx.x * blockDim.x + threadIdx.x;
    if (idx >= g * 2) return;
    int gi = idx >> 1, c = idx & 1;
    float inv = 1.0f / fmaxf(g_cnt[gi], 1.0f);
    float acc = 0.f;
#pragma unroll
    for (int k = 0; k < HD; k++)
        acc = fmaf(g_sums[gi * HD + k], Wlin[k * 2 + c], acc);
    out[idx] = fmaf(acc, inv, blin[c]);
}

extern "C" void kernel_launch(void* const* d_in, const int* in_sizes, int n_in,
                              void* d_out, int out_size) {
    const float* x      = (const float*)d_in[0];
    const int*   ei     = (const int*)d_in[1];
    const int*   batch  = (const int*)d_in[2];
    const float* ew     = (const float*)d_in[3];
    const float* W1rel  = (const float*)d_in[4];
    const float* b1     = (const float*)d_in[5];
    const float* W1root = (const float*)d_in[6];
    const float* W2rel  = (const float*)d_in[7];
    const float* b2     = (const float*)d_in[8];
    const float* W2root = (const float*)d_in[9];
    const float* W3rel  = (const float*)d_in[10];
    const float* b3     = (const float*)d_in[11];
    const float* W3root = (const float*)d_in[12];
    const float* Wlin   = (const float*)d_in[13];
    const float* blin   = (const float*)d_in[14];

    int N = in_sizes[0];        // x is [N,1]
    int E = in_sizes[3];        // edge_weight is [E]
    int G = out_size / 2;

    const int* src = ei;
    const int* dst = ei + E;
    float* out = (float*)d_out;

    init_kernel<<<256, 256>>>(N, G);
    hist_kernel<<<(E / 4 + 256) / 256, 256>>>(dst, E);
    offs_kernel<<<(N + 255) / 256, 256>>>(N);
    fill_kernel<<<(E / 2 + 256) / 256, 256>>>(src, dst, ew, E);

    layer1_kernel<<<(N * 32 + 255) / 256, 256>>>(x, batch, W1rel, b1, W1root, N);
    aggH_kernel<2><<<(N * 32 + 255) / 256, 256>>>(N);
    gemm_kernel<2><<<(N + 127) / 128, 128>>>(W2rel, W2root, b2, batch, N);
    aggH_kernel<3><<<(N * 32 + 255) / 256, 256>>>(N);
    gemm_kernel<3><<<(N + 127) / 128, 128>>>(W3rel, W3root, b3, batch, N);
    head_kernel<<<(G * 2 + 255) / 256, 256>>>(Wlin, blin, out, G);
}

// round 11
// speedup vs baseline: 1.6323x; 1.3125x over previous
#include <cuda_runtime.h>
#include <cuda_fp16.h>
#include <cstdint>

#define HD 64
#define FULL 0xFFFFFFFFu

static const int N_CAP = 100000;
static const int E_CAP = 1200000;
static const int G_CAP = 256;

// Scratch (allocation-free: __device__ globals; only referenced in device code)
__device__ int    g_deg[N_CAP];
__device__ int    g_off[N_CAP];
__device__ int    g_cur[N_CAP];
__device__ int    g_total;
__device__ int2   g_csr[E_CAP];          // {src, w bits}
__device__ __half g_h1[N_CAP * HD];      // fp16 node features (layer1 out)
__device__ __half g_h2[N_CAP * HD];      // fp16 node features (layer2 out)
__device__ float  g_agg[N_CAP * HD];     // fp32 aggregation result
__device__ float  g_sums[G_CAP * HD];
__device__ float  g_cnt[G_CAP];

__device__ __forceinline__ void red_add_v2(float* p, float x, float y) {
    asm volatile("red.global.add.v2.f32 [%0], {%1,%2};"
                 :: "l"(p), "f"(x), "f"(y) : "memory");
}

// mma.sync m16n8k16 fp16 -> fp32, accumulator via constant-indexed pointer
__device__ __forceinline__ void mma16816(float* c,
        uint32_t a0, uint32_t a1, uint32_t a2, uint32_t a3,
        uint32_t b0, uint32_t b1) {
    asm volatile(
        "mma.sync.aligned.m16n8k16.row.col.f32.f16.f16.f32 "
        "{%0,%1,%2,%3}, {%4,%5,%6,%7}, {%8,%9}, {%0,%1,%2,%3};"
        : "+f"(c[0]), "+f"(c[1]), "+f"(c[2]), "+f"(c[3])
        : "r"(a0), "r"(a1), "r"(a2), "r"(a3), "r"(b0), "r"(b1));
}

// swizzled half2 load from a [row][128] fp16 tile: 16B chunk c stored at c^(row&7)
__device__ __forceinline__ uint32_t ld_sw(const __half* base, int row, int k) {
    int chunk = (k >> 3) ^ (row & 7);
    return *(const uint32_t*)(base + row * 128 + chunk * 8 + (k & 7));
}

// ---------------- init: zero deg / sums / cnt / total ----------------
__global__ void init_kernel(int n, int g) {
    int i = blockIdx.x * blockDim.x + threadIdx.x;
    int stride = gridDim.x * blockDim.x;
    for (int k = i; k < n; k += stride) g_deg[k] = 0;
    int sv = g * HD;
    for (int k = i; k < sv; k += stride) g_sums[k] = 0.f;
    for (int k = i; k < g; k += stride) g_cnt[k] = 0.f;
    if (i == 0) g_total = 0;
}

// ---------------- CSR build ----------------
__global__ void hist_kernel(const int* __restrict__ dst, int E) {
    int t = blockIdx.x * blockDim.x + threadIdx.x;
    int i = t * 4;
    if (i + 3 < E) {
        int4 d = __ldg((const int4*)(dst + i));
        atomicAdd(&g_deg[d.x], 1);
        atomicAdd(&g_deg[d.y], 1);
        atomicAdd(&g_deg[d.z], 1);
        atomicAdd(&g_deg[d.w], 1);
    } else {
        for (int e = i; e < E; e++) atomicAdd(&g_deg[dst[e]], 1);
    }
}

__global__ void offs_kernel(int n) {
    int i = blockIdx.x * blockDim.x + threadIdx.x;
    if (i >= n) return;
    int d = g_deg[i];
    int o = atomicAdd(&g_total, d);
    g_off[i] = o;
    g_cur[i] = o;
}

__global__ void fill_kernel(const int* __restrict__ src, const int* __restrict__ dst,
                            const float* __restrict__ ew, int E) {
    int e0 = (blockIdx.x * blockDim.x + threadIdx.x) * 2;
    if (e0 >= E) return;
    int d0 = __ldg(dst + e0), s0 = __ldg(src + e0);
    float w0 = __ldg(ew + e0);
    int e1 = e0 + 1;
    int d1 = 0, s1 = 0; float w1 = 0.f;
    bool has1 = e1 < E;
    if (has1) { d1 = __ldg(dst + e1); s1 = __ldg(src + e1); w1 = __ldg(ew + e1); }
    int p0 = atomicAdd(&g_cur[d0], 1);
    g_csr[p0] = make_int2(s0, __float_as_int(w0));
    if (has1) {
        int p1 = atomicAdd(&g_cur[d1], 1);
        g_csr[p1] = make_int2(s1, __float_as_int(w1));
    }
}

// ---------------- layer 1 fused: agg (C=1 gather) + node transform + graph counts ----
__global__ void layer1_kernel(const float* __restrict__ x, const int* __restrict__ batch,
                              const float* __restrict__ Wrel, const float* __restrict__ b,
                              const float* __restrict__ Wroot, int n) {
    int gtid = blockIdx.x * blockDim.x + threadIdx.x;
    int node = gtid >> 5, lane = gtid & 31;
    if (node >= n) return;

    int off = g_off[node], deg = g_deg[node], end = off + deg;
    float a = 0.f;
    for (int i = off + lane; i < end; i += 32) {
        int2 p = __ldg(g_csr + i);
        a = fmaf(__int_as_float(p.y), __ldg(x + p.x), a);
    }
#pragma unroll
    for (int s = 16; s > 0; s >>= 1) a += __shfl_xor_sync(FULL, a, s);

    float xv = __ldg(x + node);
    float wr0 = __ldg(Wrel + lane), wr1 = __ldg(Wrel + 32 + lane);
    float wo0 = __ldg(Wroot + lane), wo1 = __ldg(Wroot + 32 + lane);
    float b0 = __ldg(b + lane), b1 = __ldg(b + 32 + lane);
    float h0 = fmaxf(fmaf(a, wr0, fmaf(xv, wo0, b0)), 0.f);
    float h1 = fmaxf(fmaf(a, wr1, fmaf(xv, wo1, b1)), 0.f);
    g_h1[node * HD + lane]      = __float2half_rn(h0);
    g_h1[node * HD + 32 + lane] = __float2half_rn(h1);
    if (lane == 0) atomicAdd(&g_cnt[batch[node]], 1.0f);
}

// ---------------- H-layer aggregation: warp-per-node, lane = channel pair ----------
template <int LAYER>
__global__ void aggH_kernel(int n) {
    const __half* __restrict__ hin = (LAYER == 2) ? g_h1 : g_h2;
    int gtid = blockIdx.x * blockDim.x + threadIdx.x;
    int node = gtid >> 5, lane = gtid & 31;
    if (node >= n) return;

    int off = g_off[node], end = off + g_deg[node];
    float a0 = 0.f, a1 = 0.f;

    int i = off;
#pragma unroll 1
    for (; i + 8 <= end; i += 8) {
        int2 p[8];
#pragma unroll
        for (int j = 0; j < 8; j++) p[j] = __ldg(g_csr + i + j);
        __half2 v[8];
#pragma unroll
        for (int j = 0; j < 8; j++)
            v[j] = __ldg((const __half2*)(hin + p[j].x * HD) + lane);
#pragma unroll
        for (int j = 0; j < 8; j++) {
            float2 f = __half22float2(v[j]);
            float w = __int_as_float(p[j].y);
            a0 = fmaf(w, f.x, a0); a1 = fmaf(w, f.y, a1);
        }
    }
#pragma unroll 1
    for (; i + 4 <= end; i += 4) {
        int2 p[4];
#pragma unroll
        for (int j = 0; j < 4; j++) p[j] = __ldg(g_csr + i + j);
        __half2 v[4];
#pragma unroll
        for (int j = 0; j < 4; j++)
            v[j] = __ldg((const __half2*)(hin + p[j].x * HD) + lane);
#pragma unroll
        for (int j = 0; j < 4; j++) {
            float2 f = __half22float2(v[j]);
            float w = __int_as_float(p[j].y);
            a0 = fmaf(w, f.x, a0); a1 = fmaf(w, f.y, a1);
        }
    }
    for (; i < end; i++) {
        int2 p = __ldg(g_csr + i);
        __half2 v = __ldg((const __half2*)(hin + p.x * HD) + lane);
        float2 f = __half22float2(v);
        float w = __int_as_float(p.y);
        a0 = fmaf(w, f.x, a0); a1 = fmaf(w, f.y, a1);
    }
    ((float2*)(g_agg + node * HD))[lane] = make_float2(a0, a1);
}

// ---------------- tensor-core node GEMM: out = [agg|h] @ [Wrel;Wroot] + b -----------
// 128-node x 64-ch tile, K=128. 8 warps in 4x2 (m x n); per-warp 2x4 m16n8k16 tiles.
// sA[128][128] fp16, sWt[64][128] fp16, both chunk-XOR swizzled. 48KB static smem.
// Fragments loaded with plain half2 loads (no ldmatrix).
// LAYER==2: relu + fp16 store to g_h2.   LAYER==3: pool via red.v2 into g_sums.
template <int LAYER>
__global__ void __launch_bounds__(256) gemm_mma_kernel(
        const float* __restrict__ Wrel, const float* __restrict__ Wroot,
        const float* __restrict__ bias, const int* __restrict__ batch, int n) {
    __shared__ __half sA[128 * 128];   // [node][k]
    __shared__ __half sWt[64 * 128];   // [j][k]  (B^T)
    const __half* Hin = (LAYER == 2) ? g_h1 : g_h2;
    int tid = threadIdx.x;
    int n0 = blockIdx.x * 128;

    // ---- stage Wt = [Wrel;Wroot]^T as fp16 (W[k][j] -> sWt[j][k]) ----
    for (int idx = tid; idx < 8192; idx += 256) {
        int k = idx >> 6, j = idx & 63;
        float wv = (k < 64) ? __ldg(Wrel + k * 64 + j) : __ldg(Wroot + (k - 64) * 64 + j);
        int chunk = (k >> 3) ^ (j & 7);
        sWt[j * 128 + chunk * 8 + (k & 7)] = __float2half_rn(wv);
    }
    // ---- stage A = [agg | h] as fp16 ----
    for (int i = tid; i < 2048; i += 256) {
        int node = i >> 4, c4 = i & 15;
        int gn = n0 + node;
        float4 v = make_float4(0.f, 0.f, 0.f, 0.f);
        if (gn < n) v = __ldg((const float4*)(g_agg + gn * HD) + c4);
        int k = c4 * 4;
        int chunk = (k >> 3) ^ (node & 7);
        __half* p = sA + node * 128 + chunk * 8 + (k & 7);
        *(__half2*)p       = __floats2half2_rn(v.x, v.y);
        *(__half2*)(p + 2) = __floats2half2_rn(v.z, v.w);
        int2 raw = make_int2(0, 0);
        if (gn < n) raw = __ldg((const int2*)(Hin + gn * HD) + c4);
        k = 64 + c4 * 4;
        chunk = (k >> 3) ^ (node & 7);
        p = sA + node * 128 + chunk * 8 + (k & 7);
        *(int*)p       = raw.x;
        *(int*)(p + 2) = raw.y;
    }
    __syncthreads();

    int lane = tid & 31, warp = tid >> 5;
    int wm = warp & 3, wn = warp >> 2;       // 4 m-warps x 2 n-warps
    int m0 = wm * 32;
    int gid = lane >> 2, tid4 = lane & 3;

    float acc[2][4][4];
#pragma unroll
    for (int mt = 0; mt < 2; mt++)
#pragma unroll
        for (int nt = 0; nt < 4; nt++)
#pragma unroll
            for (int q = 0; q < 4; q++) acc[mt][nt][q] = 0.f;

#pragma unroll
    for (int ks = 0; ks < 8; ks++) {
        int k0 = ks * 16 + tid4 * 2;
        int k1 = k0 + 8;
        uint32_t a[2][4];
#pragma unroll
        for (int mt = 0; mt < 2; mt++) {
            int row0 = m0 + mt * 16 + gid;
            int row1 = row0 + 8;
            a[mt][0] = ld_sw(sA, row0, k0);
            a[mt][1] = ld_sw(sA, row1, k0);
            a[mt][2] = ld_sw(sA, row0, k1);
            a[mt][3] = ld_sw(sA, row1, k1);
        }
#pragma unroll
        for (int nt = 0; nt < 4; nt++) {
            int j = wn * 32 + nt * 8 + gid;
            uint32_t b0 = ld_sw(sWt, j, k0);
            uint32_t b1 = ld_sw(sWt, j, k1);
            mma16816(acc[0][nt], a[0][0], a[0][1], a[0][2], a[0][3], b0, b1);
            mma16816(acc[1][nt], a[1][0], a[1][1], a[1][2], a[1][3], b0, b1);
        }
    }

    // ---- epilogue ----
    int crow = gid;                  // 0..7
    int ccol = tid4 * 2;             // even channel
#pragma unroll
    for (int nt = 0; nt < 4; nt++) {
        int j = wn * 32 + nt * 8 + ccol;
        float2 bb = __ldg((const float2*)(bias + j));
#pragma unroll
        for (int mt = 0; mt < 2; mt++) {
            int nodeA = n0 + m0 + mt * 16 + crow;
            int nodeB = nodeA + 8;
            float o0 = acc[mt][nt][0] + bb.x;
            float o1 = acc[mt][nt][1] + bb.y;
            float o2 = acc[mt][nt][2] + bb.x;
            float o3 = acc[mt][nt][3] + bb.y;
            if (LAYER == 2) {
                o0 = fmaxf(o0, 0.f); o1 = fmaxf(o1, 0.f);
                o2 = fmaxf(o2, 0.f); o3 = fmaxf(o3, 0.f);
                if (nodeA < n) *(__half2*)(g_h2 + nodeA * HD + j) = __floats2half2_rn(o0, o1);
                if (nodeB < n) *(__half2*)(g_h2 + nodeB * HD + j) = __floats2half2_rn(o2, o3);
            } else {
                if (nodeA < n) red_add_v2(g_sums + __ldg(batch + nodeA) * HD + j, o0, o1);
                if (nodeB < n) red_add_v2(g_sums + __ldg(batch + nodeB) * HD + j, o2, o3);
            }
        }
    }
}

// ---------------- head ----------------
__global__ void head_kernel(const float* __restrict__ Wlin, const float* __restrict__ blin,
                            float* __restrict__ out, int g) {
    int idx = blockIdx.x * blockDim.x + threadIdx.x;
    if (idx >= g * 2) return;
    int gi = idx >> 1, c = idx & 1;
    float inv = 1.0f / fmaxf(g_cnt[gi], 1.0f);
    float acc = 0.f;
#pragma unroll
    for (int k = 0; k < HD; k++)
        acc = fmaf(g_sums[gi * HD + k], Wlin[k * 2 + c], acc);
    out[idx] = fmaf(acc, inv, blin[c]);
}

extern "C" void kernel_launch(void* const* d_in, const int* in_sizes, int n_in,
                              void* d_out, int out_size) {
    const float* x      = (const float*)d_in[0];
    const int*   ei     = (const int*)d_in[1];
    const int*   batch  = (const int*)d_in[2];
    const float* ew     = (const float*)d_in[3];
    const float* W1rel  = (const float*)d_in[4];
    const float* b1     = (const float*)d_in[5];
    const float* W1root = (const float*)d_in[6];
    const float* W2rel  = (const float*)d_in[7];
    const float* b2     = (const float*)d_in[8];
    const float* W2root = (const float*)d_in[9];
    const float* W3rel  = (const float*)d_in[10];
    const float* b3     = (const float*)d_in[11];
    const float* W3root = (const float*)d_in[12];
    const float* Wlin   = (const float*)d_in[13];
    const float* blin   = (const float*)d_in[14];

    int N = in_sizes[0];        // x is [N,1]
    int E = in_sizes[3];        // edge_weight is [E]
    int G = out_size / 2;

    const int* src = ei;
    const int* dst = ei + E;
    float* out = (float*)d_out;

    init_kernel<<<256, 256>>>(N, G);
    hist_kernel<<<(E / 4 + 256) / 256, 256>>>(dst, E);
    offs_kernel<<<(N + 255) / 256, 256>>>(N);
    fill_kernel<<<(E / 2 + 256) / 256, 256>>>(src, dst, ew, E);

    layer1_kernel<<<(N * 32 + 255) / 256, 256>>>(x, batch, W1rel, b1, W1root, N);
    aggH_kernel<2><<<(N * 32 + 255) / 256, 256>>>(N);
    gemm_mma_kernel<2><<<(N + 127) / 128, 256>>>(W2rel, W2root, b2, batch, N);
    aggH_kernel<3><<<(N * 32 + 255) / 256, 256>>>(N);
    gemm_mma_kernel<3><<<(N + 127) / 128, 256>>>(W3rel, W3root, b3, batch, N);
    head_kernel<<<(G * 2 + 255) / 256, 256>>>(Wlin, blin, out, G);
}

// round 12
// speedup vs baseline: 1.7842x; 1.0931x over previous
#include <cuda_runtime.h>
#include <cuda_fp16.h>
#include <cstdint>

#define HD 64
#define FULL 0xFFFFFFFFu

static const int N_CAP = 100000;
static const int E_CAP = 1200000;
static const int G_CAP = 256;

// Scratch (allocation-free: __device__ globals; only referenced in device code)
__device__ int    g_deg[N_CAP];
__device__ int    g_off[N_CAP];
__device__ int    g_cur[N_CAP];
__device__ int    g_total;
__device__ int2   g_csr[E_CAP];          // {src, w bits}
__device__ __half g_h1[N_CAP * HD];      // fp16 node features (layer1 out)
__device__ __half g_h2[N_CAP * HD];      // fp16 node features (layer2 out)
__device__ __half g_agg[N_CAP * HD];     // fp16 aggregation result (quantized anyway)
__device__ __align__(16) __half g_w16[2 * 64 * 128];  // pre-swizzled [Wrel;Wroot]^T fp16, layers 2,3
__device__ float  g_sums[G_CAP * HD];
__device__ float  g_cnt[G_CAP];

__device__ __forceinline__ void red_add_v2(float* p, float x, float y) {
    asm volatile("red.global.add.v2.f32 [%0], {%1,%2};"
                 :: "l"(p), "f"(x), "f"(y) : "memory");
}

// mma.sync m16n8k16 fp16 -> fp32
__device__ __forceinline__ void mma16816(float* c,
        uint32_t a0, uint32_t a1, uint32_t a2, uint32_t a3,
        uint32_t b0, uint32_t b1) {
    asm volatile(
        "mma.sync.aligned.m16n8k16.row.col.f32.f16.f16.f32 "
        "{%0,%1,%2,%3}, {%4,%5,%6,%7}, {%8,%9}, {%0,%1,%2,%3};"
        : "+f"(c[0]), "+f"(c[1]), "+f"(c[2]), "+f"(c[3])
        : "r"(a0), "r"(a1), "r"(a2), "r"(a3), "r"(b0), "r"(b1));
}

// swizzled half2 load from a [row][128] fp16 tile: 16B chunk c stored at c^(row&7)
__device__ __forceinline__ uint32_t ld_sw(const __half* base, int row, int k) {
    int chunk = (k >> 3) ^ (row & 7);
    return *(const uint32_t*)(base + row * 128 + chunk * 8 + (k & 7));
}

// ---------------- init: zero deg / sums / cnt / total ----------------
__global__ void init_kernel(int n, int g) {
    int i = blockIdx.x * blockDim.x + threadIdx.x;
    int stride = gridDim.x * blockDim.x;
    for (int k = i; k < n; k += stride) g_deg[k] = 0;
    int sv = g * HD;
    for (int k = i; k < sv; k += stride) g_sums[k] = 0.f;
    for (int k = i; k < g; k += stride) g_cnt[k] = 0.f;
    if (i == 0) g_total = 0;
}

// ---------------- weight preconversion: [Wrel;Wroot]^T fp16, swizzled ----------------
__global__ void convw_kernel(const float* __restrict__ W2rel, const float* __restrict__ W2root,
                             const float* __restrict__ W3rel, const float* __restrict__ W3root) {
    int idx = blockIdx.x * blockDim.x + threadIdx.x;
    if (idx >= 16384) return;
    int L = idx >> 13;
    int r = idx & 8191;
    int k = r >> 6, j = r & 63;
    const float* Wrel  = L ? W3rel : W2rel;
    const float* Wroot = L ? W3root : W2root;
    float wv = (k < 64) ? __ldg(Wrel + k * 64 + j) : __ldg(Wroot + (k - 64) * 64 + j);
    int chunk = (k >> 3) ^ (j & 7);
    g_w16[L * 8192 + j * 128 + chunk * 8 + (k & 7)] = __float2half_rn(wv);
}

// ---------------- CSR build ----------------
__global__ void hist_kernel(const int* __restrict__ dst, int E) {
    int t = blockIdx.x * blockDim.x + threadIdx.x;
    int i = t * 4;
    if (i + 3 < E) {
        int4 d = __ldg((const int4*)(dst + i));
        atomicAdd(&g_deg[d.x], 1);
        atomicAdd(&g_deg[d.y], 1);
        atomicAdd(&g_deg[d.z], 1);
        atomicAdd(&g_deg[d.w], 1);
    } else {
        for (int e = i; e < E; e++) atomicAdd(&g_deg[dst[e]], 1);
    }
}

__global__ void offs_kernel(int n) {
    int i = blockIdx.x * blockDim.x + threadIdx.x;
    if (i >= n) return;
    int d = g_deg[i];
    int o = atomicAdd(&g_total, d);
    g_off[i] = o;
    g_cur[i] = o;
}

__global__ void fill_kernel(const int* __restrict__ src, const int* __restrict__ dst,
                            const float* __restrict__ ew, int E) {
    int e0 = (blockIdx.x * blockDim.x + threadIdx.x) * 2;
    if (e0 >= E) return;
    int d0 = __ldg(dst + e0), s0 = __ldg(src + e0);
    float w0 = __ldg(ew + e0);
    int e1 = e0 + 1;
    int d1 = 0, s1 = 0; float w1 = 0.f;
    bool has1 = e1 < E;
    if (has1) { d1 = __ldg(dst + e1); s1 = __ldg(src + e1); w1 = __ldg(ew + e1); }
    int p0 = atomicAdd(&g_cur[d0], 1);
    g_csr[p0] = make_int2(s0, __float_as_int(w0));
    if (has1) {
        int p1 = atomicAdd(&g_cur[d1], 1);
        g_csr[p1] = make_int2(s1, __float_as_int(w1));
    }
}

// ---------------- layer 1 fused: agg (C=1 gather) + node transform + graph counts ----
__global__ void layer1_kernel(const float* __restrict__ x, const int* __restrict__ batch,
                              const float* __restrict__ Wrel, const float* __restrict__ b,
                              const float* __restrict__ Wroot, int n) {
    int gtid = blockIdx.x * blockDim.x + threadIdx.x;
    int node = gtid >> 5, lane = gtid & 31;
    if (node >= n) return;

    int off = g_off[node], deg = g_deg[node], end = off + deg;
    float a = 0.f;
    for (int i = off + lane; i < end; i += 32) {
        int2 p = __ldg(g_csr + i);
        a = fmaf(__int_as_float(p.y), __ldg(x + p.x), a);
    }
#pragma unroll
    for (int s = 16; s > 0; s >>= 1) a += __shfl_xor_sync(FULL, a, s);

    float xv = __ldg(x + node);
    float wr0 = __ldg(Wrel + lane), wr1 = __ldg(Wrel + 32 + lane);
    float wo0 = __ldg(Wroot + lane), wo1 = __ldg(Wroot + 32 + lane);
    float b0 = __ldg(b + lane), b1 = __ldg(b + 32 + lane);
    float h0 = fmaxf(fmaf(a, wr0, fmaf(xv, wo0, b0)), 0.f);
    float h1 = fmaxf(fmaf(a, wr1, fmaf(xv, wo1, b1)), 0.f);
    g_h1[node * HD + lane]      = __float2half_rn(h0);
    g_h1[node * HD + 32 + lane] = __float2half_rn(h1);
    if (lane == 0) atomicAdd(&g_cnt[batch[node]], 1.0f);
}

// ---------------- H-layer aggregation: warp-per-node, lane = channel pair ----------
// fp32 accumulation in registers; fp16 store (same quantization the GEMM did anyway)
template <int LAYER>
__global__ void aggH_kernel(int n) {
    const __half* __restrict__ hin = (LAYER == 2) ? g_h1 : g_h2;
    int gtid = blockIdx.x * blockDim.x + threadIdx.x;
    int node = gtid >> 5, lane = gtid & 31;
    if (node >= n) return;

    int off = g_off[node], end = off + g_deg[node];
    float a0 = 0.f, a1 = 0.f;

    int i = off;
#pragma unroll 1
    for (; i + 8 <= end; i += 8) {
        int2 p[8];
#pragma unroll
        for (int j = 0; j < 8; j++) p[j] = __ldg(g_csr + i + j);
        __half2 v[8];
#pragma unroll
        for (int j = 0; j < 8; j++)
            v[j] = __ldg((const __half2*)(hin + p[j].x * HD) + lane);
#pragma unroll
        for (int j = 0; j < 8; j++) {
            float2 f = __half22float2(v[j]);
            float w = __int_as_float(p[j].y);
            a0 = fmaf(w, f.x, a0); a1 = fmaf(w, f.y, a1);
        }
    }
#pragma unroll 1
    for (; i + 4 <= end; i += 4) {
        int2 p[4];
#pragma unroll
        for (int j = 0; j < 4; j++) p[j] = __ldg(g_csr + i + j);
        __half2 v[4];
#pragma unroll
        for (int j = 0; j < 4; j++)
            v[j] = __ldg((const __half2*)(hin + p[j].x * HD) + lane);
#pragma unroll
        for (int j = 0; j < 4; j++) {
            float2 f = __half22float2(v[j]);
            float w = __int_as_float(p[j].y);
            a0 = fmaf(w, f.x, a0); a1 = fmaf(w, f.y, a1);
        }
    }
    for (; i < end; i++) {
        int2 p = __ldg(g_csr + i);
        __half2 v = __ldg((const __half2*)(hin + p.x * HD) + lane);
        float2 f = __half22float2(v);
        float w = __int_as_float(p.y);
        a0 = fmaf(w, f.x, a0); a1 = fmaf(w, f.y, a1);
    }
    ((__half2*)(g_agg + node * HD))[lane] = __floats2half2_rn(a0, a1);
}

// ---------------- tensor-core node GEMM: out = [agg|h] @ [Wrel;Wroot] + b -----------
// 128-node x 64-ch tile, K=128. sWt copied pre-swizzled from g_w16; sA pure int2 copies.
// LAYER==2: relu + fp16 store to g_h2.   LAYER==3: pool via red.v2 into g_sums.
template <int LAYER>
__global__ void __launch_bounds__(256) gemm_mma_kernel(
        const float* __restrict__ bias, const int* __restrict__ batch, int n) {
    __shared__ __align__(16) __half sA[128 * 128];   // [node][k], swizzled
    __shared__ __align__(16) __half sWt[64 * 128];   // [j][k],    swizzled
    const __half* Hin = (LAYER == 2) ? g_h1 : g_h2;
    const __half* Wt = g_w16 + ((LAYER == 2) ? 0 : 8192);
    int tid = threadIdx.x;
    int n0 = blockIdx.x * 128;

    // ---- stage Wt: straight 16KB copy (pre-swizzled) ----
#pragma unroll
    for (int i = 0; i < 4; i++)
        ((int4*)sWt)[tid + i * 256] = __ldg((const int4*)Wt + tid + i * 256);

    // ---- stage A = [agg | h] fp16 (pure copies into swizzle) ----
    for (int i = tid; i < 2048; i += 256) {
        int node = i >> 4, c4 = i & 15;
        int gn = n0 + node;
        int2 ra = make_int2(0, 0), rh = make_int2(0, 0);
        if (gn < n) {
            ra = __ldg((const int2*)(g_agg + gn * HD) + c4);
            rh = __ldg((const int2*)(Hin + gn * HD) + c4);
        }
        int k = c4 * 4;
        int chunk = (k >> 3) ^ (node & 7);
        __half* p = sA + node * 128 + chunk * 8 + (k & 7);
        *(int*)p       = ra.x;
        *(int*)(p + 2) = ra.y;
        k = 64 + c4 * 4;
        chunk = (k >> 3) ^ (node & 7);
        p = sA + node * 128 + chunk * 8 + (k & 7);
        *(int*)p       = rh.x;
        *(int*)(p + 2) = rh.y;
    }
    __syncthreads();

    int lane = tid & 31, warp = tid >> 5;
    int wm = warp & 3, wn = warp >> 2;       // 4 m-warps x 2 n-warps
    int m0 = wm * 32;
    int gid = lane >> 2, tid4 = lane & 3;

    float acc[2][4][4];
#pragma unroll
    for (int mt = 0; mt < 2; mt++)
#pragma unroll
        for (int nt = 0; nt < 4; nt++)
#pragma unroll
            for (int q = 0; q < 4; q++) acc[mt][nt][q] = 0.f;

#pragma unroll
    for (int ks = 0; ks < 8; ks++) {
        int k0 = ks * 16 + tid4 * 2;
        int k1 = k0 + 8;
        uint32_t a[2][4];
#pragma unroll
        for (int mt = 0; mt < 2; mt++) {
            int row0 = m0 + mt * 16 + gid;
            int row1 = row0 + 8;
            a[mt][0] = ld_sw(sA, row0, k0);
            a[mt][1] = ld_sw(sA, row1, k0);
            a[mt][2] = ld_sw(sA, row0, k1);
            a[mt][3] = ld_sw(sA, row1, k1);
        }
#pragma unroll
        for (int nt = 0; nt < 4; nt++) {
            int j = wn * 32 + nt * 8 + gid;
            uint32_t b0 = ld_sw(sWt, j, k0);
            uint32_t b1 = ld_sw(sWt, j, k1);
            mma16816(acc[0][nt], a[0][0], a[0][1], a[0][2], a[0][3], b0, b1);
            mma16816(acc[1][nt], a[1][0], a[1][1], a[1][2], a[1][3], b0, b1);
        }
    }

    // ---- epilogue ----
    int crow = gid;
    int ccol = tid4 * 2;
#pragma unroll
    for (int nt = 0; nt < 4; nt++) {
        int j = wn * 32 + nt * 8 + ccol;
        float2 bb = __ldg((const float2*)(bias + j));
#pragma unroll
        for (int mt = 0; mt < 2; mt++) {
            int nodeA = n0 + m0 + mt * 16 + crow;
            int nodeB = nodeA + 8;
            float o0 = acc[mt][nt][0] + bb.x;
            float o1 = acc[mt][nt][1] + bb.y;
            float o2 = acc[mt][nt][2] + bb.x;
            float o3 = acc[mt][nt][3] + bb.y;
            if (LAYER == 2) {
                o0 = fmaxf(o0, 0.f); o1 = fmaxf(o1, 0.f);
                o2 = fmaxf(o2, 0.f); o3 = fmaxf(o3, 0.f);
                if (nodeA < n) *(__half2*)(g_h2 + nodeA * HD + j) = __floats2half2_rn(o0, o1);
                if (nodeB < n) *(__half2*)(g_h2 + nodeB * HD + j) = __floats2half2_rn(o2, o3);
            } else {
                if (nodeA < n) red_add_v2(g_sums + __ldg(batch + nodeA) * HD + j, o0, o1);
                if (nodeB < n) red_add_v2(g_sums + __ldg(batch + nodeB) * HD + j, o2, o3);
            }
        }
    }
}

// ---------------- head ----------------
__global__ void head_kernel(const float* __restrict__ Wlin, const float* __restrict__ blin,
                            float* __restrict__ out, int g) {
    int idx = blockIdx.x * blockDim.x + threadIdx.x;
    if (idx >= g * 2) return;
    int gi = idx >> 1, c = idx & 1;
    float inv = 1.0f / fmaxf(g_cnt[gi], 1.0f);
    float acc = 0.f;
#pragma unroll
    for (int k = 0; k < HD; k++)
        acc = fmaf(g_sums[gi * HD + k], Wlin[k * 2 + c], acc);
    out[idx] = fmaf(acc, inv, blin[c]);
}

extern "C" void kernel_launch(void* const* d_in, const int* in_sizes, int n_in,
                              void* d_out, int out_size) {
    const float* x      = (const float*)d_in[0];
    const int*   ei     = (const int*)d_in[1];
    const int*   batch  = (const int*)d_in[2];
    const float* ew     = (const float*)d_in[3];
    const float* W1rel  = (const float*)d_in[4];
    const float* b1     = (const float*)d_in[5];
    const float* W1root = (const float*)d_in[6];
    const float* W2rel  = (const float*)d_in[7];
    const float* b2     = (const float*)d_in[8];
    const float* W2root = (const float*)d_in[9];
    const float* W3rel  = (const float*)d_in[10];
    const float* b3     = (const float*)d_in[11];
    const float* W3root = (const float*)d_in[12];
    const float* Wlin   = (const float*)d_in[13];
    const float* blin   = (const float*)d_in[14];

    int N = in_sizes[0];        // x is [N,1]
    int E = in_sizes[3];        // edge_weight is [E]
    int G = out_size / 2;

    const int* src = ei;
    const int* dst = ei + E;
    float* out = (float*)d_out;

    init_kernel<<<256, 256>>>(N, G);
    convw_kernel<<<64, 256>>>(W2rel, W2root, W3rel, W3root);
    hist_kernel<<<(E / 4 + 256) / 256, 256>>>(dst, E);
    offs_kernel<<<(N + 255) / 256, 256>>>(N);
    fill_kernel<<<(E / 2 + 256) / 256, 256>>>(src, dst, ew, E);

    layer1_kernel<<<(N * 32 + 255) / 256, 256>>>(x, batch, W1rel, b1, W1root, N);
    aggH_kernel<2><<<(N * 32 + 255) / 256, 256>>>(N);
    gemm_mma_kernel<2><<<(N + 127) / 128, 256>>>(b2, batch, N);
    aggH_kernel<3><<<(N * 32 + 255) / 256, 256>>>(N);
    gemm_mma_kernel<3><<<(N + 127) / 128, 256>>>(b3, batch, N);
    head_kernel<<<(G * 2 + 255) / 256, 256>>>(Wlin, blin, out, G);
}

// round 13
// speedup vs baseline: 1.9284x; 1.0808x over previous
#include <cuda_runtime.h>
#include <cuda_fp16.h>
#include <cstdint>

#define HD 64
#define FULL 0xFFFFFFFFu

static const int N_CAP = 100000;
static const int E_CAP = 1200000;
static const int G_CAP = 256;

// Scratch (allocation-free: __device__ globals; only referenced in device code)
__device__ int    g_deg[N_CAP];
__device__ int    g_off[N_CAP];
__device__ int    g_cur[N_CAP];
__device__ int    g_total;
__device__ int2   g_csr[E_CAP];          // {src, w bits}
__device__ float  g_agg1[N_CAP];         // layer-1 scalar aggregation (filled by fill_kernel)
__device__ __half g_h1[N_CAP * HD];      // fp16 node features (layer1 out)
__device__ __half g_h2[N_CAP * HD];      // fp16 node features (layer2 out)
__device__ __half g_agg[N_CAP * HD];     // fp16 aggregation result
__device__ __align__(16) __half g_w16[2 * 64 * 128];  // pre-swizzled [Wrel;Wroot]^T fp16
__device__ float  g_sums[G_CAP * HD];
__device__ float  g_cnt[G_CAP];

__device__ __forceinline__ void red_add_v2(float* p, float x, float y) {
    asm volatile("red.global.add.v2.f32 [%0], {%1,%2};"
                 :: "l"(p), "f"(x), "f"(y) : "memory");
}
__device__ __forceinline__ void red_add_f(float* p, float x) {
    asm volatile("red.global.add.f32 [%0], %1;" :: "l"(p), "f"(x) : "memory");
}

// mma.sync m16n8k16 fp16 -> fp32
__device__ __forceinline__ void mma16816(float* c,
        uint32_t a0, uint32_t a1, uint32_t a2, uint32_t a3,
        uint32_t b0, uint32_t b1) {
    asm volatile(
        "mma.sync.aligned.m16n8k16.row.col.f32.f16.f16.f32 "
        "{%0,%1,%2,%3}, {%4,%5,%6,%7}, {%8,%9}, {%0,%1,%2,%3};"
        : "+f"(c[0]), "+f"(c[1]), "+f"(c[2]), "+f"(c[3])
        : "r"(a0), "r"(a1), "r"(a2), "r"(a3), "r"(b0), "r"(b1));
}

// swizzled half2 load from a [row][128] fp16 tile: 16B chunk c stored at c^(row&7)
__device__ __forceinline__ uint32_t ld_sw(const __half* base, int row, int k) {
    int chunk = (k >> 3) ^ (row & 7);
    return *(const uint32_t*)(base + row * 128 + chunk * 8 + (k & 7));
}

// ---------------- init + weight preconversion ----------------
__global__ void init_kernel(const float* __restrict__ W2rel, const float* __restrict__ W2root,
                            const float* __restrict__ W3rel, const float* __restrict__ W3root,
                            int n, int g) {
    int i = blockIdx.x * blockDim.x + threadIdx.x;
    int stride = gridDim.x * blockDim.x;
    for (int k = i; k < n; k += stride) { g_deg[k] = 0; g_agg1[k] = 0.f; }
    int sv = g * HD;
    for (int k = i; k < sv; k += stride) g_sums[k] = 0.f;
    for (int k = i; k < g; k += stride) g_cnt[k] = 0.f;
    if (i == 0) g_total = 0;
    for (int idx = i; idx < 16384; idx += stride) {
        int L = idx >> 13;
        int r = idx & 8191;
        int k = r >> 6, j = r & 63;
        const float* Wrel  = L ? W3rel : W2rel;
        const float* Wroot = L ? W3root : W2root;
        float wv = (k < 64) ? __ldg(Wrel + k * 64 + j) : __ldg(Wroot + (k - 64) * 64 + j);
        int chunk = (k >> 3) ^ (j & 7);
        g_w16[L * 8192 + j * 128 + chunk * 8 + (k & 7)] = __float2half_rn(wv);
    }
}

// ---------------- CSR build ----------------
__global__ void hist_kernel(const int* __restrict__ dst, int E) {
    int t = blockIdx.x * blockDim.x + threadIdx.x;
    int i = t * 4;
    if (i + 3 < E) {
        int4 d = __ldg((const int4*)(dst + i));
        atomicAdd(&g_deg[d.x], 1);
        atomicAdd(&g_deg[d.y], 1);
        atomicAdd(&g_deg[d.z], 1);
        atomicAdd(&g_deg[d.w], 1);
    } else {
        for (int e = i; e < E; e++) atomicAdd(&g_deg[dst[e]], 1);
    }
}

// warp-aggregated: inclusive scan, one atomicAdd per warp
__global__ void offs_kernel(int n) {
    int i = blockIdx.x * blockDim.x + threadIdx.x;
    int lane = threadIdx.x & 31;
    int d = (i < n) ? g_deg[i] : 0;
    int s = d;
#pragma unroll
    for (int o = 1; o < 32; o <<= 1) {
        int t = __shfl_up_sync(FULL, s, o);
        if (lane >= o) s += t;
    }
    int wsum = __shfl_sync(FULL, s, 31);
    int base = 0;
    if (lane == 31) base = atomicAdd(&g_total, wsum);
    base = __shfl_sync(FULL, base, 31);
    if (i < n) {
        int o = base + s - d;    // exclusive
        g_off[i] = o;
        g_cur[i] = o;
    }
}

// fill CSR + layer-1 scalar aggregation (agg1[dst] += w * x[src])
__global__ void fill_kernel(const int* __restrict__ src, const int* __restrict__ dst,
                            const float* __restrict__ ew, const float* __restrict__ x, int E) {
    int e0 = (blockIdx.x * blockDim.x + threadIdx.x) * 2;
    if (e0 >= E) return;
    int d0 = __ldg(dst + e0), s0 = __ldg(src + e0);
    float w0 = __ldg(ew + e0);
    int e1 = e0 + 1;
    int d1 = 0, s1 = 0; float w1 = 0.f;
    bool has1 = e1 < E;
    if (has1) { d1 = __ldg(dst + e1); s1 = __ldg(src + e1); w1 = __ldg(ew + e1); }
    float x0 = __ldg(x + s0);
    float x1 = has1 ? __ldg(x + s1) : 0.f;
    int p0 = atomicAdd(&g_cur[d0], 1);
    g_csr[p0] = make_int2(s0, __float_as_int(w0));
    red_add_f(&g_agg1[d0], w0 * x0);
    if (has1) {
        int p1 = atomicAdd(&g_cur[d1], 1);
        g_csr[p1] = make_int2(s1, __float_as_int(w1));
        red_add_f(&g_agg1[d1], w1 * x1);
    }
}

// ---------------- layer 1 node transform (agg1 precomputed by fill) ----------------
// thread per (node, 8 channels)
__global__ void node1_kernel(const float* __restrict__ x, const int* __restrict__ batch,
                             const float* __restrict__ Wrel, const float* __restrict__ b,
                             const float* __restrict__ Wroot, int n) {
    int idx = blockIdx.x * blockDim.x + threadIdx.x;
    if (idx >= n * 8) return;
    int node = idx >> 3, c8 = idx & 7;
    float a = g_agg1[node];
    float xv = __ldg(x + node);
    float4 wr0 = __ldg((const float4*)Wrel + c8 * 2);
    float4 wr1 = __ldg((const float4*)Wrel + c8 * 2 + 1);
    float4 wo0 = __ldg((const float4*)Wroot + c8 * 2);
    float4 wo1 = __ldg((const float4*)Wroot + c8 * 2 + 1);
    float4 bb0 = __ldg((const float4*)b + c8 * 2);
    float4 bb1 = __ldg((const float4*)b + c8 * 2 + 1);
    float h0 = fmaxf(fmaf(a, wr0.x, fmaf(xv, wo0.x, bb0.x)), 0.f);
    float h1 = fmaxf(fmaf(a, wr0.y, fmaf(xv, wo0.y, bb0.y)), 0.f);
    float h2 = fmaxf(fmaf(a, wr0.z, fmaf(xv, wo0.z, bb0.z)), 0.f);
    float h3 = fmaxf(fmaf(a, wr0.w, fmaf(xv, wo0.w, bb0.w)), 0.f);
    float h4 = fmaxf(fmaf(a, wr1.x, fmaf(xv, wo1.x, bb1.x)), 0.f);
    float h5 = fmaxf(fmaf(a, wr1.y, fmaf(xv, wo1.y, bb1.y)), 0.f);
    float h6 = fmaxf(fmaf(a, wr1.z, fmaf(xv, wo1.z, bb1.z)), 0.f);
    float h7 = fmaxf(fmaf(a, wr1.w, fmaf(xv, wo1.w, bb1.w)), 0.f);
    __half2 p0 = __floats2half2_rn(h0, h1);
    __half2 p1 = __floats2half2_rn(h2, h3);
    __half2 p2 = __floats2half2_rn(h4, h5);
    __half2 p3 = __floats2half2_rn(h6, h7);
    *(int4*)(g_h1 + node * HD + c8 * 8) =
        make_int4(*(int*)&p0, *(int*)&p1, *(int*)&p2, *(int*)&p3);
    if (c8 == 0) atomicAdd(&g_cnt[batch[node]], 1.0f);
}

// ---------------- H-layer aggregation: warp-per-node, lane = channel pair ----------
template <int LAYER>
__global__ void aggH_kernel(int n) {
    const __half* __restrict__ hin = (LAYER == 2) ? g_h1 : g_h2;
    int gtid = blockIdx.x * blockDim.x + threadIdx.x;
    int node = gtid >> 5, lane = gtid & 31;
    if (node >= n) return;

    int off = g_off[node], end = off + g_deg[node];
    float a0 = 0.f, a1 = 0.f;

    int i = off;
#pragma unroll 1
    for (; i + 8 <= end; i += 8) {
        int2 p[8];
#pragma unroll
        for (int j = 0; j < 8; j++) p[j] = __ldg(g_csr + i + j);
        __half2 v[8];
#pragma unroll
        for (int j = 0; j < 8; j++)
            v[j] = __ldg((const __half2*)(hin + p[j].x * HD) + lane);
#pragma unroll
        for (int j = 0; j < 8; j++) {
            float2 f = __half22float2(v[j]);
            float w = __int_as_float(p[j].y);
            a0 = fmaf(w, f.x, a0); a1 = fmaf(w, f.y, a1);
        }
    }
#pragma unroll 1
    for (; i + 4 <= end; i += 4) {
        int2 p[4];
#pragma unroll
        for (int j = 0; j < 4; j++) p[j] = __ldg(g_csr + i + j);
        __half2 v[4];
#pragma unroll
        for (int j = 0; j < 4; j++)
            v[j] = __ldg((const __half2*)(hin + p[j].x * HD) + lane);
#pragma unroll
        for (int j = 0; j < 4; j++) {
            float2 f = __half22float2(v[j]);
            float w = __int_as_float(p[j].y);
            a0 = fmaf(w, f.x, a0); a1 = fmaf(w, f.y, a1);
        }
    }
    for (; i < end; i++) {
        int2 p = __ldg(g_csr + i);
        __half2 v = __ldg((const __half2*)(hin + p.x * HD) + lane);
        float2 f = __half22float2(v);
        float w = __int_as_float(p.y);
        a0 = fmaf(w, f.x, a0); a1 = fmaf(w, f.y, a1);
    }
    ((__half2*)(g_agg + node * HD))[lane] = __floats2half2_rn(a0, a1);
}

// ---------------- tensor-core node GEMM: out = [agg|h] @ [Wrel;Wroot] + b -----------
template <int LAYER>
__global__ void __launch_bounds__(256) gemm_mma_kernel(
        const float* __restrict__ bias, const int* __restrict__ batch, int n) {
    __shared__ __align__(16) __half sA[128 * 128];   // [node][k], swizzled
    __shared__ __align__(16) __half sWt[64 * 128];   // [j][k],    swizzled
    const __half* Hin = (LAYER == 2) ? g_h1 : g_h2;
    const __half* Wt = g_w16 + ((LAYER == 2) ? 0 : 8192);
    int tid = threadIdx.x;
    int n0 = blockIdx.x * 128;

#pragma unroll
    for (int i = 0; i < 4; i++)
        ((int4*)sWt)[tid + i * 256] = __ldg((const int4*)Wt + tid + i * 256);

    for (int i = tid; i < 2048; i += 256) {
        int node = i >> 4, c4 = i & 15;
        int gn = n0 + node;
        int2 ra = make_int2(0, 0), rh = make_int2(0, 0);
        if (gn < n) {
            ra = __ldg((const int2*)(g_agg + gn * HD) + c4);
            rh = __ldg((const int2*)(Hin + gn * HD) + c4);
        }
        int k = c4 * 4;
        int chunk = (k >> 3) ^ (node & 7);
        __half* p = sA + node * 128 + chunk * 8 + (k & 7);
        *(int*)p       = ra.x;
        *(int*)(p + 2) = ra.y;
        k = 64 + c4 * 4;
        chunk = (k >> 3) ^ (node & 7);
        p = sA + node * 128 + chunk * 8 + (k & 7);
        *(int*)p       = rh.x;
        *(int*)(p + 2) = rh.y;
    }
    __syncthreads();

    int lane = tid & 31, warp = tid >> 5;
    int wm = warp & 3, wn = warp >> 2;
    int m0 = wm * 32;
    int gid = lane >> 2, tid4 = lane & 3;

    float acc[2][4][4];
#pragma unroll
    for (int mt = 0; mt < 2; mt++)
#pragma unroll
        for (int nt = 0; nt < 4; nt++)
#pragma unroll
            for (int q = 0; q < 4; q++) acc[mt][nt][q] = 0.f;

#pragma unroll
    for (int ks = 0; ks < 8; ks++) {
        int k0 = ks * 16 + tid4 * 2;
        int k1 = k0 + 8;
        uint32_t a[2][4];
#pragma unroll
        for (int mt = 0; mt < 2; mt++) {
            int row0 = m0 + mt * 16 + gid;
            int row1 = row0 + 8;
            a[mt][0] = ld_sw(sA, row0, k0);
            a[mt][1] = ld_sw(sA, row1, k0);
            a[mt][2] = ld_sw(sA, row0, k1);
            a[mt][3] = ld_sw(sA, row1, k1);
        }
#pragma unroll
        for (int nt = 0; nt < 4; nt++) {
            int j = wn * 32 + nt * 8 + gid;
            uint32_t b0 = ld_sw(sWt, j, k0);
            uint32_t b1 = ld_sw(sWt, j, k1);
            mma16816(acc[0][nt], a[0][0], a[0][1], a[0][2], a[0][3], b0, b1);
            mma16816(acc[1][nt], a[1][0], a[1][1], a[1][2], a[1][3], b0, b1);
        }
    }

    int crow = gid;
    int ccol = tid4 * 2;
#pragma unroll
    for (int nt = 0; nt < 4; nt++) {
        int j = wn * 32 + nt * 8 + ccol;
        float2 bb = __ldg((const float2*)(bias + j));
#pragma unroll
        for (int mt = 0; mt < 2; mt++) {
            int nodeA = n0 + m0 + mt * 16 + crow;
            int nodeB = nodeA + 8;
            float o0 = acc[mt][nt][0] + bb.x;
            float o1 = acc[mt][nt][1] + bb.y;
            float o2 = acc[mt][nt][2] + bb.x;
            float o3 = acc[mt][nt][3] + bb.y;
            if (LAYER == 2) {
                o0 = fmaxf(o0, 0.f); o1 = fmaxf(o1, 0.f);
                o2 = fmaxf(o2, 0.f); o3 = fmaxf(o3, 0.f);
                if (nodeA < n) *(__half2*)(g_h2 + nodeA * HD + j) = __floats2half2_rn(o0, o1);
                if (nodeB < n) *(__half2*)(g_h2 + nodeB * HD + j) = __floats2half2_rn(o2, o3);
            } else {
                if (nodeA < n) red_add_v2(g_sums + __ldg(batch + nodeA) * HD + j, o0, o1);
                if (nodeB < n) red_add_v2(g_sums + __ldg(batch + nodeB) * HD + j, o2, o3);
            }
        }
    }
}

// ---------------- head ----------------
__global__ void head_kernel(const float* __restrict__ Wlin, const float* __restrict__ blin,
                            float* __restrict__ out, int g) {
    int idx = blockIdx.x * blockDim.x + threadIdx.x;
    if (idx >= g * 2) return;
    int gi = idx >> 1, c = idx & 1;
    float inv = 1.0f / fmaxf(g_cnt[gi], 1.0f);
    float acc = 0.f;
#pragma unroll
    for (int k = 0; k < HD; k++)
        acc = fmaf(g_sums[gi * HD + k], Wlin[k * 2 + c], acc);
    out[idx] = fmaf(acc, inv, blin[c]);
}

extern "C" void kernel_launch(void* const* d_in, const int* in_sizes, int n_in,
                              void* d_out, int out_size) {
    const float* x      = (const float*)d_in[0];
    const int*   ei     = (const int*)d_in[1];
    const int*   batch  = (const int*)d_in[2];
    const float* ew     = (const float*)d_in[3];
    const float* W1rel  = (const float*)d_in[4];
    const float* b1     = (const float*)d_in[5];
    const float* W1root = (const float*)d_in[6];
    const float* W2rel  = (const float*)d_in[7];
    const float* b2     = (const float*)d_in[8];
    const float* W2root = (const float*)d_in[9];
    const float* W3rel  = (const float*)d_in[10];
    const float* b3     = (const float*)d_in[11];
    const float* W3root = (const float*)d_in[12];
    const float* Wlin   = (const float*)d_in[13];
    const float* blin   = (const float*)d_in[14];

    int N = in_sizes[0];        // x is [N,1]
    int E = in_sizes[3];        // edge_weight is [E]
    int G = out_size / 2;

    const int* src = ei;
    const int* dst = ei + E;
    float* out = (float*)d_out;

    init_kernel<<<256, 256>>>(W2rel, W2root, W3rel, W3root, N, G);
    hist_kernel<<<(E / 4 + 256) / 256, 256>>>(dst, E);
    offs_kernel<<<(N + 255) / 256, 256>>>(N);
    fill_kernel<<<(E / 2 + 256) / 256, 256>>>(src, dst, ew, x, E);

    node1_kernel<<<(N * 8 + 255) / 256, 256>>>(x, batch, W1rel, b1, W1root, N);
    aggH_kernel<2><<<(N * 32 + 255) / 256, 256>>>(N);
    gemm_mma_kernel<2><<<(N + 127) / 128, 256>>>(b2, batch, N);
    aggH_kernel<3><<<(N * 32 + 255) / 256, 256>>>(N);
    gemm_mma_kernel<3><<<(N + 127) / 128, 256>>>(b3, batch, N);
    head_kernel<<<(G * 2 + 255) / 256, 256>>>(Wlin, blin, out, G);
}